// round 12
// baseline (speedup 1.0000x reference)
#include <cuda_runtime.h>
#include <math_constants.h>

#define BSZ   64
#define NGEN  128
#define NCLS  30
#define SEQ   2048
#define G     16
#define TGOLD (BSZ * G)                              // 1024
#define COST_ELEMS ((size_t)BSZ * NGEN * TGOLD)      // 8388608
#define NITER 16                                     // 8 dists x 2 rows
#define NLSA  BSZ                                    // 64 lsa blocks (first)
#define BLOCKS_PER_EX 64                             // 128 rows / 2

struct Ptrs {
    const float* pos[8];   // 8 positional logit tensors [BSZ*NGEN, SEQ]
    const int*   gidx[8];  // 8 gold index arrays [TGOLD]
};

__device__ int g_cnt[BSZ];

__global__ void init_kernel() {
    if (threadIdx.x < BSZ) g_cnt[threadIdx.x] = 0;
}

// ---------------------------------------------------------------------------
// helpers
// ---------------------------------------------------------------------------
__device__ __forceinline__ unsigned smem_u32(const void* p) {
    unsigned a;
    asm("{ .reg .u64 t; cvta.to.shared.u64 t, %1; cvt.u32.u64 %0, t; }"
        : "=r"(a) : "l"(p));
    return a;
}
__device__ __forceinline__ void cp_async16(unsigned dst, const float* src) {
    asm volatile("cp.async.cg.shared.global [%0], [%1], 16;" :: "r"(dst), "l"(src));
}
__device__ __forceinline__ unsigned fkey(float x) {
    int b = __float_as_int(x);
    return (unsigned)(b ^ ((b >> 31) | 0x80000000));
}
__device__ __forceinline__ float funkey(unsigned k) {
    int b = (k & 0x80000000u) ? (int)(k ^ 0x80000000u) : (int)(~k);
    return __int_as_float(b);
}
__device__ __forceinline__ unsigned redux_min_u32(unsigned x) {
    unsigned r;
    asm volatile("redux.sync.min.u32 %0, %1, 0xffffffff;" : "=r"(r) : "r"(x));
    return r;
}
// release add: publishes this thread's prior (hb-ordered) writes, NO L1D flush
__device__ __forceinline__ void red_release_add(int* p, int v) {
    asm volatile("red.release.gpu.global.add.s32 [%0], %1;" :: "l"(p), "r"(v)
                 : "memory");
}
// acquire load: pairs with the release add
__device__ __forceinline__ int ld_acquire(const int* p) {
    int v;
    asm volatile("ld.acquire.gpu.global.s32 %0, [%1];" : "=r"(v) : "l"(p)
                 : "memory");
    return v;
}

// ---------------------------------------------------------------------------
// Fused kernel.
//  bid <  64 : lsa role — resident from wave 1; lane 0 polls g_cnt[b] with
//              ld.acquire until its example's 64 cost blocks signalled, then
//              solves LAPJV (f32, register state, redux argmin — validated
//              identical assignment to the f64 reference).
//  bid >= 64 : cost role — TWO (b,n) rows, 3-stage depth-2 cp.async
//              pipeline, exp at use site, ONE barrier/iteration, gold-index
//              int4 loaded once per dist (identical arithmetic -> bit-
//              identical cost). Completion: __syncthreads (hb from all
//              threads' STGs) + tid0 red.release — NO __threadfence, so no
//              CCTL.IVALL L1-flush evicting neighbor blocks' caches.
// ---------------------------------------------------------------------------
__global__ __launch_bounds__(256)
void fused_kernel(const float* __restrict__ prel, const int* __restrict__ grel,
                  Ptrs ptrs, float* __restrict__ out) {
    __shared__ __align__(16) char smem_raw[24896];

    if (blockIdx.x >= NLSA) {
        // ========================= cost role =========================
        float (*stage)[SEQ] = (float (*)[SEQ])smem_raw;              // 24 KB
        float (*relp)[32]   = (float (*)[32])(smem_raw + 24576);     // 256 B
        float (*red)[8]     = (float (*)[8])(smem_raw + 24832);      // 64 B

        const int row0 = (blockIdx.x - NLSA) * 2;
        const int tid  = threadIdx.x;
        const int w    = tid >> 5;
        const int lane = tid & 31;

        const unsigned sbase = smem_u32(&stage[0][0]);

        // prologue: iterations 0,1 in flight (depth-2)
        #pragma unroll
        for (int k = 0; k < 2; k++) {
            const float* src = ptrs.pos[k >> 1] + (size_t)(row0 + (k & 1)) * SEQ;
            unsigned dst = sbase + (unsigned)(k * (SEQ * 4)) + (unsigned)(tid * 16);
            cp_async16(dst, src + 4 * tid);
            cp_async16(dst + 4096, src + 1024 + 4 * tid);
            asm volatile("cp.async.commit_group;");
        }

        // rel-class softmax: warp 0 -> row0, warp 1 -> row0+1
        if (tid < 64) {
            float e = (lane < NCLS) ? __expf(prel[(size_t)(row0 + w) * NCLS + lane]) : 0.f;
            float s = e;
            #pragma unroll
            for (int o = 16; o; o >>= 1) s += __shfl_xor_sync(0xffffffffu, s, o);
            if (lane < NCLS) relp[w][lane] = e / s;
        }
        __syncthreads();

        const int4 gr = ((const int4*)grel)[tid];
        float acc[2][4];
        #pragma unroll
        for (int r = 0; r < 2; r++) {
            acc[r][0] = relp[r][gr.x];
            acc[r][1] = relp[r][gr.y];
            acc[r][2] = relp[r][gr.z];
            acc[r][3] = relp[r][gr.w];
        }

        int4 gi;
        #pragma unroll
        for (int k = 0; k < NITER; k++) {
            const int d  = k >> 1;
            const int r  = k & 1;
            const int sb = k % 3;
            const int pb = k & 1;

            if (k < 15) asm volatile("cp.async.wait_group 1;");
            else        asm volatile("cp.async.wait_group 0;");

            if (r == 0) gi = ((const int4*)ptrs.gidx[d])[tid];

            const float4* sp = (const float4*)&stage[sb][0];
            float4 x0 = sp[tid];
            float4 x1 = sp[tid + 256];
            float lsum = (__expf(x0.x) + __expf(x0.y)) + (__expf(x0.z) + __expf(x0.w))
                       + (__expf(x1.x) + __expf(x1.y)) + (__expf(x1.z) + __expf(x1.w));
            #pragma unroll
            for (int o = 16; o; o >>= 1) lsum += __shfl_xor_sync(0xffffffffu, lsum, o);
            if (lane == 0) red[pb][w] = lsum;
            __syncthreads();   // red visible; cp.asyncs of iter k published;
                               // gathers of k-1 ordered before k+2 refill

            float s = ((red[pb][0] + red[pb][1]) + (red[pb][2] + red[pb][3]))
                    + ((red[pb][4] + red[pb][5]) + (red[pb][6] + red[pb][7]));
            float inv = 1.0f / s;

            acc[r][0] += __expf(stage[sb][gi.x]) * inv;
            acc[r][1] += __expf(stage[sb][gi.y]) * inv;
            acc[r][2] += __expf(stage[sb][gi.z]) * inv;
            acc[r][3] += __expf(stage[sb][gi.w]) * inv;

            if (k + 2 < NITER) {
                const int kn = k + 2;
                const float* src = ptrs.pos[kn >> 1] + (size_t)(row0 + (kn & 1)) * SEQ;
                unsigned dst = sbase + (unsigned)((kn % 3) * (SEQ * 4))
                                     + (unsigned)(tid * 16);
                cp_async16(dst, src + 4 * tid);
                cp_async16(dst + 4096, src + 1024 + 4 * tid);
                asm volatile("cp.async.commit_group;");
            }
        }

        #pragma unroll
        for (int r = 0; r < 2; r++) {
            float4 res = make_float4(-acc[r][0], -acc[r][1], -acc[r][2], -acc[r][3]);
            ((float4*)(out + (size_t)(row0 + r) * TGOLD))[tid] = res;
        }

        // publish: syncthreads gives hb from ALL threads' STGs to tid0;
        // the release-add carries that hb to the acquiring lsa block.
        __syncthreads();
        if (tid == 0) red_release_add(&g_cnt[row0 >> 7], 1);

    } else {
        // ========================= lsa role =========================
        if (threadIdx.x >= 32) return;
        const int b = blockIdx.x;
        const int lane = threadIdx.x;

        float* Cf = (float*)smem_raw;                 // 8 KB
        int*   x  = (int*)(smem_raw + 8192);          // 64 B

        if (lane == 0) {
            while (ld_acquire(&g_cnt[b]) < BLOCKS_PER_EX) __nanosleep(128);
        }
        __syncwarp();

        const float* cost = out;
        for (int j = lane; j < NGEN; j += 32) {
            const float4* src = (const float4*)(cost + ((size_t)(b * NGEN + j)) * TGOLD + b * G);
            #pragma unroll
            for (int q = 0; q < 4; q++) {
                float4 f = src[q];
                Cf[(q * 4 + 0) * NGEN + j] = f.x;
                Cf[(q * 4 + 1) * NGEN + j] = f.y;
                Cf[(q * 4 + 2) * NGEN + j] = f.z;
                Cf[(q * 4 + 3) * NGEN + j] = f.w;
            }
        }
        __syncwarp();

        float vreg[4];                 // v[j], j = lane + 32*t (ZERO init)
        int   yreg[4];                 // col -> row (-1 free)
        #pragma unroll
        for (int t = 0; t < 4; t++) { vreg[t] = 0.f; yreg[t] = -1; }

        for (int f = 0; f < G; f++) {
            float dreg[4];
            int   pr[4];
            #pragma unroll
            for (int t = 0; t < 4; t++) {
                dreg[t] = Cf[f * NGEN + lane + 32 * t] - vreg[t];
                pr[t] = f;
            }
            unsigned scan = 0;
            int jmin;
            float mu;

            while (true) {
                unsigned bestk = 0xFFFFFFFFu;
                unsigned bestj = 0xFFFFFFFFu;
                #pragma unroll
                for (int t = 0; t < 4; t++) {
                    if (!((scan >> t) & 1u)) {
                        unsigned k = fkey(dreg[t]);
                        if (k < bestk) { bestk = k; bestj = (unsigned)(lane + 32 * t); }
                    }
                }
                unsigned kmin = redux_min_u32(bestk);
                unsigned j1   = redux_min_u32((bestk == kmin) ? bestj : 0xFFFFFFFFu);
                mu   = funkey(kmin);
                jmin = (int)j1;

                const int tt = jmin >> 5, sl = jmin & 31;
                if (sl == lane) scan |= 1u << tt;

                int   ysel = (tt == 0) ? yreg[0] : (tt == 1) ? yreg[1]
                           : (tt == 2) ? yreg[2] : yreg[3];
                float vsel = (tt == 0) ? vreg[0] : (tt == 1) ? vreg[1]
                           : (tt == 2) ? vreg[2] : vreg[3];
                int   i1 = __shfl_sync(0xffffffffu, ysel, sl);
                float vj = __shfl_sync(0xffffffffu, vsel, sl);
                if (i1 < 0) break;

                float ui = Cf[i1 * NGEN + jmin] - vj;

                #pragma unroll
                for (int t = 0; t < 4; t++) {
                    if (!((scan >> t) & 1u)) {
                        int j = lane + 32 * t;
                        float nd = mu + (Cf[i1 * NGEN + j] - vreg[t]) - ui;
                        if (nd < dreg[t]) { dreg[t] = nd; pr[t] = i1; }
                    }
                }
            }

            #pragma unroll
            for (int t = 0; t < 4; t++)
                if ((scan >> t) & 1u) vreg[t] += dreg[t] - mu;

            int j = jmin;
            while (true) {
                const int tt = j >> 5, sl = j & 31;
                int psel = (tt == 0) ? pr[0] : (tt == 1) ? pr[1]
                         : (tt == 2) ? pr[2] : pr[3];
                int i = __shfl_sync(0xffffffffu, psel, sl);
                if ((j & 31) == lane) yreg[j >> 5] = i;   // y[j] = i
                int jn = 0;
                if (lane == 0) {
                    jn = (i == f) ? -1 : x[i];
                    x[i] = j;
                }
                jn = __shfl_sync(0xffffffffu, jn, 0);
                if (i == f) break;
                j = jn;
            }
            __syncwarp();
        }

        // transposed return: col[i] = x[i]; order = argsort(col)
        if (lane < G) {
            float* rows_out = (float*)(out + COST_ELEMS);
            float* cols_out = rows_out + (size_t)BSZ * G;
            int c = x[lane];
            int rank = 0;
            #pragma unroll
            for (int r2 = 0; r2 < G; r2++) rank += (x[r2] < c) ? 1 : 0;
            rows_out[b * G + rank] = (float)c;
            cols_out[b * G + rank] = (float)lane;
        }
    }
}

// ---------------------------------------------------------------------------
// Launch
// ---------------------------------------------------------------------------
extern "C" void kernel_launch(void* const* d_in, const int* in_sizes, int n_in,
                              void* d_out, int out_size) {
    const float* prel = (const float*)d_in[0];
    Ptrs ptrs;
    for (int d = 0; d < 8; d++) ptrs.pos[d]  = (const float*)d_in[1 + d];
    const int* grel = (const int*)d_in[9];
    for (int d = 0; d < 8; d++) ptrs.gidx[d] = (const int*)d_in[10 + d];

    float* out = (float*)d_out;

    init_kernel<<<1, 64>>>();
    fused_kernel<<<NLSA + (BSZ * NGEN) / 2, 256>>>(prel, grel, ptrs, out);
}

// round 13
// speedup vs baseline: 1.1737x; 1.1737x over previous
#include <cuda_runtime.h>
#include <math_constants.h>

#define BSZ   64
#define NGEN  128
#define NCLS  30
#define SEQ   2048
#define G     16
#define TGOLD (BSZ * G)                              // 1024
#define COST_ELEMS ((size_t)BSZ * NGEN * TGOLD)      // 8388608
#define NITER 16                                     // 8 dists x 2 rows
#define BLOCKS_PER_EX 64                             // 128 rows / 2

struct Ptrs {
    const float* pos[8];   // 8 positional logit tensors [BSZ*NGEN, SEQ]
    const int*   gidx[8];  // 8 gold index arrays [TGOLD]
};

__device__ int g_cnt[BSZ];

__global__ void init_kernel() {
    if (threadIdx.x < BSZ) g_cnt[threadIdx.x] = 0;
}

// ---------------------------------------------------------------------------
// helpers
// ---------------------------------------------------------------------------
__device__ __forceinline__ unsigned smem_u32(const void* p) {
    unsigned a;
    asm("{ .reg .u64 t; cvta.to.shared.u64 t, %1; cvt.u32.u64 %0, t; }"
        : "=r"(a) : "l"(p));
    return a;
}
__device__ __forceinline__ void cp_async16(unsigned dst, const float* src) {
    asm volatile("cp.async.cg.shared.global [%0], [%1], 16;" :: "r"(dst), "l"(src));
}
__device__ __forceinline__ unsigned fkey(float x) {
    int b = __float_as_int(x);
    return (unsigned)(b ^ ((b >> 31) | 0x80000000));
}
__device__ __forceinline__ float funkey(unsigned k) {
    int b = (k & 0x80000000u) ? (int)(k ^ 0x80000000u) : (int)(~k);
    return __int_as_float(b);
}
__device__ __forceinline__ unsigned redux_min_u32(unsigned x) {
    unsigned r;
    asm volatile("redux.sync.min.u32 %0, %1, 0xffffffff;" : "=r"(r) : "r"(x));
    return r;
}
// acq_rel fetch-add: release publishes this block's (syncthreads-ordered)
// writes; acquire makes all prior releasers' writes visible to the winner.
__device__ __forceinline__ int atom_acqrel_add(int* p, int v) {
    int old;
    asm volatile("atom.acq_rel.gpu.global.add.s32 %0, [%1], %2;"
                 : "=r"(old) : "l"(p), "r"(v) : "memory");
    return old;
}
__device__ __forceinline__ int ld_acquire(const int* p) {
    int v;
    asm volatile("ld.acquire.gpu.global.s32 %0, [%1];" : "=r"(v) : "l"(p)
                 : "memory");
    return v;
}

// ---------------------------------------------------------------------------
// Fused cost+lsa, last-block-takes-over (NO waiter blocks, NO spinning).
// Every block: cost for TWO (b,n) rows (R11 3-stage depth-2 cp.async
// pipeline, exp at use site, ONE barrier/iteration — bit-identical cost
// output). Then syncthreads + tid0 acq_rel fetch-add on g_cnt[example].
// The block seeing old==63 has acquire-visibility of all 128 rows and its
// warp 0 solves the example's LAPJV in place (smem reused, warps 1-7 exit).
// ---------------------------------------------------------------------------
__global__ __launch_bounds__(256)
void cost_lsa_kernel(const float* __restrict__ prel, const int* __restrict__ grel,
                     Ptrs ptrs, float* __restrict__ out) {
    __shared__ __align__(16) char smem_raw[24896];

    // ========================= cost phase =========================
    {
        float (*stage)[SEQ] = (float (*)[SEQ])smem_raw;              // 24 KB
        float (*relp)[32]   = (float (*)[32])(smem_raw + 24576);     // 256 B
        float (*red)[8]     = (float (*)[8])(smem_raw + 24832);      // 64 B

        const int row0 = blockIdx.x * 2;
        const int tid  = threadIdx.x;
        const int w    = tid >> 5;
        const int lane = tid & 31;

        const unsigned sbase = smem_u32(&stage[0][0]);

        // prologue: iterations 0,1 in flight (depth-2)
        #pragma unroll
        for (int k = 0; k < 2; k++) {
            const float* src = ptrs.pos[k >> 1] + (size_t)(row0 + (k & 1)) * SEQ;
            unsigned dst = sbase + (unsigned)(k * (SEQ * 4)) + (unsigned)(tid * 16);
            cp_async16(dst, src + 4 * tid);
            cp_async16(dst + 4096, src + 1024 + 4 * tid);
            asm volatile("cp.async.commit_group;");
        }

        // rel-class softmax: warp 0 -> row0, warp 1 -> row0+1
        if (tid < 64) {
            float e = (lane < NCLS) ? __expf(prel[(size_t)(row0 + w) * NCLS + lane]) : 0.f;
            float s = e;
            #pragma unroll
            for (int o = 16; o; o >>= 1) s += __shfl_xor_sync(0xffffffffu, s, o);
            if (lane < NCLS) relp[w][lane] = e / s;
        }
        __syncthreads();

        const int4 gr = ((const int4*)grel)[tid];
        float acc[2][4];
        #pragma unroll
        for (int r = 0; r < 2; r++) {
            acc[r][0] = relp[r][gr.x];
            acc[r][1] = relp[r][gr.y];
            acc[r][2] = relp[r][gr.z];
            acc[r][3] = relp[r][gr.w];
        }

        int4 gi;
        #pragma unroll
        for (int k = 0; k < NITER; k++) {
            const int d  = k >> 1;
            const int r  = k & 1;
            const int sb = k % 3;
            const int pb = k & 1;

            if (k < 15) asm volatile("cp.async.wait_group 1;");
            else        asm volatile("cp.async.wait_group 0;");

            if (r == 0) gi = ((const int4*)ptrs.gidx[d])[tid];

            const float4* sp = (const float4*)&stage[sb][0];
            float4 x0 = sp[tid];
            float4 x1 = sp[tid + 256];
            float lsum = (__expf(x0.x) + __expf(x0.y)) + (__expf(x0.z) + __expf(x0.w))
                       + (__expf(x1.x) + __expf(x1.y)) + (__expf(x1.z) + __expf(x1.w));
            #pragma unroll
            for (int o = 16; o; o >>= 1) lsum += __shfl_xor_sync(0xffffffffu, lsum, o);
            if (lane == 0) red[pb][w] = lsum;
            __syncthreads();   // red visible; cp.asyncs of iter k published;
                               // gathers of k-1 ordered before k+2 refill

            float s = ((red[pb][0] + red[pb][1]) + (red[pb][2] + red[pb][3]))
                    + ((red[pb][4] + red[pb][5]) + (red[pb][6] + red[pb][7]));
            float inv = 1.0f / s;

            acc[r][0] += __expf(stage[sb][gi.x]) * inv;
            acc[r][1] += __expf(stage[sb][gi.y]) * inv;
            acc[r][2] += __expf(stage[sb][gi.z]) * inv;
            acc[r][3] += __expf(stage[sb][gi.w]) * inv;

            if (k + 2 < NITER) {
                const int kn = k + 2;
                const float* src = ptrs.pos[kn >> 1] + (size_t)(row0 + (kn & 1)) * SEQ;
                unsigned dst = sbase + (unsigned)((kn % 3) * (SEQ * 4))
                                     + (unsigned)(tid * 16);
                cp_async16(dst, src + 4 * tid);
                cp_async16(dst + 4096, src + 1024 + 4 * tid);
                asm volatile("cp.async.commit_group;");
            }
        }

        #pragma unroll
        for (int r = 0; r < 2; r++) {
            float4 res = make_float4(-acc[r][0], -acc[r][1], -acc[r][2], -acc[r][3]);
            ((float4*)(out + (size_t)(row0 + r) * TGOLD))[tid] = res;
        }
    }

    // ================= completion + last-block takeover =================
    const int b = (int)(blockIdx.x >> 6);            // example index
    __syncthreads();                                  // all STGs hb-before tid0
    int last = 0;
    if (threadIdx.x == 0)
        last = (atom_acqrel_add(&g_cnt[b], 1) == BLOCKS_PER_EX - 1);
    if (threadIdx.x >= 32) return;                    // warps 1-7 done

    const int lane = threadIdx.x;
    last = __shfl_sync(0xffffffffu, last, 0);
    if (!last) return;

    // every lane establishes its own acquire on the counter
    (void)ld_acquire(&g_cnt[b]);

    // ========================= lsa phase (warp 0) =========================
    float* Cf = (float*)smem_raw;                 // 8 KB (reuse)
    int*   x  = (int*)(smem_raw + 8192);          // 64 B (row -> col)

    const float* cost = out;
    for (int j = lane; j < NGEN; j += 32) {
        const float4* src = (const float4*)(cost + ((size_t)(b * NGEN + j)) * TGOLD + b * G);
        #pragma unroll
        for (int q = 0; q < 4; q++) {
            float4 f = src[q];
            Cf[(q * 4 + 0) * NGEN + j] = f.x;
            Cf[(q * 4 + 1) * NGEN + j] = f.y;
            Cf[(q * 4 + 2) * NGEN + j] = f.z;
            Cf[(q * 4 + 3) * NGEN + j] = f.w;
        }
    }
    __syncwarp();

    float vreg[4];                 // v[j], j = lane + 32*t (ZERO init:
    int   yreg[4];                 //   rectangular dual feasibility)
    #pragma unroll
    for (int t = 0; t < 4; t++) { vreg[t] = 0.f; yreg[t] = -1; }

    for (int f = 0; f < G; f++) {
        float dreg[4];
        int   pr[4];
        #pragma unroll
        for (int t = 0; t < 4; t++) {
            dreg[t] = Cf[f * NGEN + lane + 32 * t] - vreg[t];
            pr[t] = f;
        }
        unsigned scan = 0;
        int jmin;
        float mu;

        while (true) {
            unsigned bestk = 0xFFFFFFFFu;
            unsigned bestj = 0xFFFFFFFFu;
            #pragma unroll
            for (int t = 0; t < 4; t++) {
                if (!((scan >> t) & 1u)) {
                    unsigned k = fkey(dreg[t]);
                    if (k < bestk) { bestk = k; bestj = (unsigned)(lane + 32 * t); }
                }
            }
            unsigned kmin = redux_min_u32(bestk);
            unsigned j1   = redux_min_u32((bestk == kmin) ? bestj : 0xFFFFFFFFu);
            mu   = funkey(kmin);
            jmin = (int)j1;

            const int tt = jmin >> 5, sl = jmin & 31;
            if (sl == lane) scan |= 1u << tt;

            int   ysel = (tt == 0) ? yreg[0] : (tt == 1) ? yreg[1]
                       : (tt == 2) ? yreg[2] : yreg[3];
            float vsel = (tt == 0) ? vreg[0] : (tt == 1) ? vreg[1]
                       : (tt == 2) ? vreg[2] : vreg[3];
            int   i1 = __shfl_sync(0xffffffffu, ysel, sl);
            float vj = __shfl_sync(0xffffffffu, vsel, sl);
            if (i1 < 0) break;

            float ui = Cf[i1 * NGEN + jmin] - vj;

            #pragma unroll
            for (int t = 0; t < 4; t++) {
                if (!((scan >> t) & 1u)) {
                    int j = lane + 32 * t;
                    float nd = mu + (Cf[i1 * NGEN + j] - vreg[t]) - ui;
                    if (nd < dreg[t]) { dreg[t] = nd; pr[t] = i1; }
                }
            }
        }

        // deferred potential update over scanned columns
        #pragma unroll
        for (int t = 0; t < 4; t++)
            if ((scan >> t) & 1u) vreg[t] += dreg[t] - mu;

        // augment along pred chain
        int j = jmin;
        while (true) {
            const int tt = j >> 5, sl = j & 31;
            int psel = (tt == 0) ? pr[0] : (tt == 1) ? pr[1]
                     : (tt == 2) ? pr[2] : pr[3];
            int i = __shfl_sync(0xffffffffu, psel, sl);
            if ((j & 31) == lane) yreg[j >> 5] = i;   // y[j] = i
            int jn = 0;
            if (lane == 0) {
                jn = (i == f) ? -1 : x[i];
                x[i] = j;
            }
            jn = __shfl_sync(0xffffffffu, jn, 0);
            if (i == f) break;
            j = jn;
        }
        __syncwarp();
    }

    // transposed return: col[i] = x[i]; order = argsort(col)
    if (lane < G) {
        float* rows_out = (float*)(out + COST_ELEMS);
        float* cols_out = rows_out + (size_t)BSZ * G;
        int c = x[lane];
        int rank = 0;
        #pragma unroll
        for (int r2 = 0; r2 < G; r2++) rank += (x[r2] < c) ? 1 : 0;
        rows_out[b * G + rank] = (float)c;
        cols_out[b * G + rank] = (float)lane;
    }
}

// ---------------------------------------------------------------------------
// Launch
// ---------------------------------------------------------------------------
extern "C" void kernel_launch(void* const* d_in, const int* in_sizes, int n_in,
                              void* d_out, int out_size) {
    const float* prel = (const float*)d_in[0];
    Ptrs ptrs;
    for (int d = 0; d < 8; d++) ptrs.pos[d]  = (const float*)d_in[1 + d];
    const int* grel = (const int*)d_in[9];
    for (int d = 0; d < 8; d++) ptrs.gidx[d] = (const int*)d_in[10 + d];

    float* out = (float*)d_out;

    init_kernel<<<1, 64>>>();
    cost_lsa_kernel<<<(BSZ * NGEN) / 2, 256>>>(prel, grel, ptrs, out);
}

// round 14
// speedup vs baseline: 1.2238x; 1.0426x over previous
#include <cuda_runtime.h>
#include <math_constants.h>

#define BSZ   64
#define NGEN  128
#define NCLS  30
#define SEQ   2048
#define G     16
#define TGOLD (BSZ * G)                              // 1024
#define COST_ELEMS ((size_t)BSZ * NGEN * TGOLD)      // 8388608
#define NITER 16                                     // 8 dists x 2 rows
#define BLOCKS_PER_EX 64                             // 128 rows / 2
#define STAGE_BYTES (SEQ * 4)                        // 8192

struct Ptrs {
    const float* pos[8];   // 8 positional logit tensors [BSZ*NGEN, SEQ]
    const int*   gidx[8];  // 8 gold index arrays [TGOLD]
};

// Monotonic per-example counters: NEVER reset. Each launch adds exactly 64
// per example; completion test is (old % 64 == 63) -> identical behavior on
// every call (graph-replay deterministic), no init kernel needed.
__device__ unsigned g_cnt[BSZ];

// ---------------------------------------------------------------------------
// helpers
// ---------------------------------------------------------------------------
__device__ __forceinline__ unsigned smem_u32(const void* p) {
    unsigned a;
    asm("{ .reg .u64 t; cvta.to.shared.u64 t, %1; cvt.u32.u64 %0, t; }"
        : "=r"(a) : "l"(p));
    return a;
}
__device__ __forceinline__ unsigned fkey(float x) {
    int b = __float_as_int(x);
    return (unsigned)(b ^ ((b >> 31) | 0x80000000));
}
__device__ __forceinline__ float funkey(unsigned k) {
    int b = (k & 0x80000000u) ? (int)(k ^ 0x80000000u) : (int)(~k);
    return __int_as_float(b);
}
__device__ __forceinline__ unsigned redux_min_u32(unsigned x) {
    unsigned r;
    asm volatile("redux.sync.min.u32 %0, %1, 0xffffffff;" : "=r"(r) : "r"(x));
    return r;
}
__device__ __forceinline__ unsigned atom_acqrel_add_u32(unsigned* p, unsigned v) {
    unsigned old;
    asm volatile("atom.acq_rel.gpu.global.add.u32 %0, [%1], %2;"
                 : "=r"(old) : "l"(p), "r"(v) : "memory");
    return old;
}
__device__ __forceinline__ unsigned ld_acquire_u32(const unsigned* p) {
    unsigned v;
    asm volatile("ld.acquire.gpu.global.u32 %0, [%1];" : "=r"(v) : "l"(p)
                 : "memory");
    return v;
}
__device__ __forceinline__ void mbar_init(unsigned mbar, unsigned count) {
    asm volatile("mbarrier.init.shared.b64 [%0], %1;" :: "r"(mbar), "r"(count)
                 : "memory");
}
__device__ __forceinline__ void mbar_expect_tx(unsigned mbar, unsigned tx) {
    asm volatile("mbarrier.arrive.expect_tx.shared.b64 _, [%0], %1;"
                 :: "r"(mbar), "r"(tx) : "memory");
}
__device__ __forceinline__ void bulk_g2s(unsigned dst, const void* src,
                                         unsigned bytes, unsigned mbar) {
    asm volatile(
        "cp.async.bulk.shared::cluster.global.mbarrier::complete_tx::bytes "
        "[%0], [%1], %2, [%3];"
        :: "r"(dst), "l"(src), "r"(bytes), "r"(mbar) : "memory");
}
__device__ __forceinline__ void mbar_wait(unsigned mbar, unsigned parity) {
    unsigned done;
    asm volatile(
        "{\n\t.reg .pred p;\n\t"
        "mbarrier.try_wait.parity.acquire.cta.shared::cta.b64 p, [%1], %2;\n\t"
        "selp.b32 %0, 1, 0, p;\n\t}"
        : "=r"(done) : "r"(mbar), "r"(parity) : "memory");
    while (!done) {
        asm volatile(
            "{\n\t.reg .pred p;\n\t"
            "mbarrier.try_wait.parity.acquire.cta.shared::cta.b64 p, [%1], %2, 0x989680;\n\t"
            "selp.b32 %0, 1, 0, p;\n\t}"
            : "=r"(done) : "r"(mbar), "r"(parity) : "memory");
    }
}

// ---------------------------------------------------------------------------
// Fused cost+lsa, last-block-takes-over. Cost staging via cp.async.bulk
// (one 8 KB TMA-path copy per block-iteration + mbarrier) instead of
// per-thread LDGSTS — frees LSU issue + L1tex wavefront slots for the
// gather/sum LDS stream. 3 stages, depth-2; ONE __syncthreads/iteration
// (also orders gathers of iter k-1 before the k+2 refill of that slot).
// Arithmetic identical to R13 -> bit-identical cost output.
// ---------------------------------------------------------------------------
__global__ __launch_bounds__(256)
void cost_lsa_kernel(const float* __restrict__ prel, const int* __restrict__ grel,
                     Ptrs ptrs, float* __restrict__ out) {
    __shared__ __align__(128) char smem_raw[3 * STAGE_BYTES + 32 + 256 + 64];
    // layout: [0, 24576) stages; [24576, 24600) 3 mbars; [24608,24864) relp;
    //         [24864, 24928) red

    // ========================= cost phase =========================
    {
        float (*stage)[SEQ] = (float (*)[SEQ])smem_raw;
        float (*relp)[32]   = (float (*)[32])(smem_raw + 3 * STAGE_BYTES + 32);
        float (*red)[8]     = (float (*)[8])(smem_raw + 3 * STAGE_BYTES + 32 + 256);

        const int row0 = blockIdx.x * 2;
        const int tid  = threadIdx.x;
        const int w    = tid >> 5;
        const int lane = tid & 31;

        const unsigned sbase = smem_u32(&stage[0][0]);
        const unsigned mbase = sbase + 3 * STAGE_BYTES;

        if (tid == 0) {
            mbar_init(mbase + 0, 1);
            mbar_init(mbase + 8, 1);
            mbar_init(mbase + 16, 1);
        }
        __syncthreads();            // mbar init visible to all waiters

        // prologue: iterations 0,1 in flight (depth-2), issued by tid 0
        if (tid == 0) {
            #pragma unroll
            for (int k = 0; k < 2; k++) {
                const float* src = ptrs.pos[k >> 1] + (size_t)(row0 + (k & 1)) * SEQ;
                mbar_expect_tx(mbase + 8u * k, STAGE_BYTES);
                bulk_g2s(sbase + (unsigned)k * STAGE_BYTES, src, STAGE_BYTES,
                         mbase + 8u * k);
            }
        }

        // rel-class softmax: warp 0 -> row0, warp 1 -> row0+1 (overlaps loads)
        if (tid < 64) {
            float e = (lane < NCLS) ? __expf(prel[(size_t)(row0 + w) * NCLS + lane]) : 0.f;
            float s = e;
            #pragma unroll
            for (int o = 16; o; o >>= 1) s += __shfl_xor_sync(0xffffffffu, s, o);
            if (lane < NCLS) relp[w][lane] = e / s;
        }
        __syncthreads();

        const int4 gr = ((const int4*)grel)[tid];
        float acc[2][4];
        #pragma unroll
        for (int r = 0; r < 2; r++) {
            acc[r][0] = relp[r][gr.x];
            acc[r][1] = relp[r][gr.y];
            acc[r][2] = relp[r][gr.z];
            acc[r][3] = relp[r][gr.w];
        }

        int4 gi;
        #pragma unroll
        for (int k = 0; k < NITER; k++) {
            const int d  = k >> 1;
            const int r  = k & 1;
            const int sb = k % 3;
            const int pb = k & 1;

            // wait for this iteration's bulk copy (phase flips per slot reuse)
            mbar_wait(mbase + 8u * sb, (unsigned)((k / 3) & 1));

            if (r == 0) gi = ((const int4*)ptrs.gidx[d])[tid];

            const float4* sp = (const float4*)&stage[sb][0];
            float4 x0 = sp[tid];
            float4 x1 = sp[tid + 256];
            float lsum = (__expf(x0.x) + __expf(x0.y)) + (__expf(x0.z) + __expf(x0.w))
                       + (__expf(x1.x) + __expf(x1.y)) + (__expf(x1.z) + __expf(x1.w));
            #pragma unroll
            for (int o = 16; o; o >>= 1) lsum += __shfl_xor_sync(0xffffffffu, lsum, o);
            if (lane == 0) red[pb][w] = lsum;
            __syncthreads();   // red visible; gathers of k-1 ordered before
                               // the k+2 refill below (same stage slot)

            float s = ((red[pb][0] + red[pb][1]) + (red[pb][2] + red[pb][3]))
                    + ((red[pb][4] + red[pb][5]) + (red[pb][6] + red[pb][7]));
            float inv = 1.0f / s;

            acc[r][0] += __expf(stage[sb][gi.x]) * inv;
            acc[r][1] += __expf(stage[sb][gi.y]) * inv;
            acc[r][2] += __expf(stage[sb][gi.z]) * inv;
            acc[r][3] += __expf(stage[sb][gi.w]) * inv;

            // refill: iteration k+2 into slot (k+2)%3
            if (k + 2 < NITER && tid == 0) {
                const int kn = k + 2;
                const float* src = ptrs.pos[kn >> 1] + (size_t)(row0 + (kn & 1)) * SEQ;
                const unsigned slot = (unsigned)(kn % 3);
                mbar_expect_tx(mbase + 8u * slot, STAGE_BYTES);
                bulk_g2s(sbase + slot * STAGE_BYTES, src, STAGE_BYTES,
                         mbase + 8u * slot);
            }
        }

        #pragma unroll
        for (int r = 0; r < 2; r++) {
            float4 res = make_float4(-acc[r][0], -acc[r][1], -acc[r][2], -acc[r][3]);
            ((float4*)(out + (size_t)(row0 + r) * TGOLD))[tid] = res;
        }
    }

    // ================= completion + last-block takeover =================
    const int b = (int)(blockIdx.x >> 6);            // example index
    __syncthreads();                                  // all STGs hb-before tid0
    int last = 0;
    if (threadIdx.x == 0)
        last = ((atom_acqrel_add_u32(&g_cnt[b], 1u) & 63u) == 63u);
    if (threadIdx.x >= 32) return;                    // warps 1-7 done

    const int lane = threadIdx.x;
    last = __shfl_sync(0xffffffffu, last, 0);
    if (!last) return;

    (void)ld_acquire_u32(&g_cnt[b]);                  // per-lane acquire

    // ========================= lsa phase (warp 0) =========================
    float* Cf = (float*)smem_raw;                 // 8 KB (reuse)
    int*   x  = (int*)(smem_raw + 8192);          // 64 B (row -> col)

    const float* cost = out;
    for (int j = lane; j < NGEN; j += 32) {
        const float4* src = (const float4*)(cost + ((size_t)(b * NGEN + j)) * TGOLD + b * G);
        #pragma unroll
        for (int q = 0; q < 4; q++) {
            float4 f = src[q];
            Cf[(q * 4 + 0) * NGEN + j] = f.x;
            Cf[(q * 4 + 1) * NGEN + j] = f.y;
            Cf[(q * 4 + 2) * NGEN + j] = f.z;
            Cf[(q * 4 + 3) * NGEN + j] = f.w;
        }
    }
    __syncwarp();

    float vreg[4];                 // v[j], j = lane + 32*t (ZERO init:
    int   yreg[4];                 //   rectangular dual feasibility)
    #pragma unroll
    for (int t = 0; t < 4; t++) { vreg[t] = 0.f; yreg[t] = -1; }

    for (int f = 0; f < G; f++) {
        float dreg[4];
        int   pr[4];
        #pragma unroll
        for (int t = 0; t < 4; t++) {
            dreg[t] = Cf[f * NGEN + lane + 32 * t] - vreg[t];
            pr[t] = f;
        }
        unsigned scan = 0;
        int jmin;
        float mu;

        while (true) {
            unsigned bestk = 0xFFFFFFFFu;
            unsigned bestj = 0xFFFFFFFFu;
            #pragma unroll
            for (int t = 0; t < 4; t++) {
                if (!((scan >> t) & 1u)) {
                    unsigned k = fkey(dreg[t]);
                    if (k < bestk) { bestk = k; bestj = (unsigned)(lane + 32 * t); }
                }
            }
            unsigned kmin = redux_min_u32(bestk);
            unsigned j1   = redux_min_u32((bestk == kmin) ? bestj : 0xFFFFFFFFu);
            mu   = funkey(kmin);
            jmin = (int)j1;

            const int tt = jmin >> 5, sl = jmin & 31;
            if (sl == lane) scan |= 1u << tt;

            int   ysel = (tt == 0) ? yreg[0] : (tt == 1) ? yreg[1]
                       : (tt == 2) ? yreg[2] : yreg[3];
            float vsel = (tt == 0) ? vreg[0] : (tt == 1) ? vreg[1]
                       : (tt == 2) ? vreg[2] : vreg[3];
            int   i1 = __shfl_sync(0xffffffffu, ysel, sl);
            float vj = __shfl_sync(0xffffffffu, vsel, sl);
            if (i1 < 0) break;

            float ui = Cf[i1 * NGEN + jmin] - vj;

            #pragma unroll
            for (int t = 0; t < 4; t++) {
                if (!((scan >> t) & 1u)) {
                    int j = lane + 32 * t;
                    float nd = mu + (Cf[i1 * NGEN + j] - vreg[t]) - ui;
                    if (nd < dreg[t]) { dreg[t] = nd; pr[t] = i1; }
                }
            }
        }

        // deferred potential update over scanned columns
        #pragma unroll
        for (int t = 0; t < 4; t++)
            if ((scan >> t) & 1u) vreg[t] += dreg[t] - mu;

        // augment along pred chain
        int j = jmin;
        while (true) {
            const int tt = j >> 5, sl = j & 31;
            int psel = (tt == 0) ? pr[0] : (tt == 1) ? pr[1]
                     : (tt == 2) ? pr[2] : pr[3];
            int i = __shfl_sync(0xffffffffu, psel, sl);
            if ((j & 31) == lane) yreg[j >> 5] = i;   // y[j] = i
            int jn = 0;
            if (lane == 0) {
                jn = (i == f) ? -1 : x[i];
                x[i] = j;
            }
            jn = __shfl_sync(0xffffffffu, jn, 0);
            if (i == f) break;
            j = jn;
        }
        __syncwarp();
    }

    // transposed return: col[i] = x[i]; order = argsort(col)
    if (lane < G) {
        float* rows_out = (float*)(out + COST_ELEMS);
        float* cols_out = rows_out + (size_t)BSZ * G;
        int c = x[lane];
        int rank = 0;
        #pragma unroll
        for (int r2 = 0; r2 < G; r2++) rank += (x[r2] < c) ? 1 : 0;
        rows_out[b * G + rank] = (float)c;
        cols_out[b * G + rank] = (float)lane;
    }
}

// ---------------------------------------------------------------------------
// Launch — single kernel, no init (modulo counters)
// ---------------------------------------------------------------------------
extern "C" void kernel_launch(void* const* d_in, const int* in_sizes, int n_in,
                              void* d_out, int out_size) {
    const float* prel = (const float*)d_in[0];
    Ptrs ptrs;
    for (int d = 0; d < 8; d++) ptrs.pos[d]  = (const float*)d_in[1 + d];
    const int* grel = (const int*)d_in[9];
    for (int d = 0; d < 8; d++) ptrs.gidx[d] = (const int*)d_in[10 + d];

    float* out = (float*)d_out;

    cost_lsa_kernel<<<(BSZ * NGEN) / 2, 256>>>(prel, grel, ptrs, out);
}

// round 15
// speedup vs baseline: 1.2484x; 1.0201x over previous
#include <cuda_runtime.h>
#include <math_constants.h>

#define BSZ   64
#define NGEN  128
#define NCLS  30
#define SEQ   2048
#define G     16
#define TGOLD (BSZ * G)                              // 1024
#define COST_ELEMS ((size_t)BSZ * NGEN * TGOLD)      // 8388608
#define NITER 16                                     // 8 dists x 2 rows
#define BLOCKS_PER_EX 64                             // 128 rows / 2
#define STAGE_BYTES (SEQ * 4)                        // 8192

struct Ptrs {
    const float* pos[8];   // 8 positional logit tensors [BSZ*NGEN, SEQ]
    const int*   gidx[8];  // 8 gold index arrays [TGOLD]
};

// Monotonic per-example counters: NEVER reset. Each launch adds exactly 64
// per example; completion test is (old % 64 == 63) -> identical behavior on
// every call (graph-replay deterministic), no init kernel needed.
__device__ unsigned g_cnt[BSZ];

// Compact per-example diagonal cost block C[i][j] = cost[b, j, b*G+i],
// stored [b][j][i] (8 KB/example). Written by the 4 owning threads of each
// cost block (same float4 bits as `out`), read only by the lsa winner.
__device__ float g_diag[BSZ][NGEN][G];               // 512 KB

// ---------------------------------------------------------------------------
// helpers
// ---------------------------------------------------------------------------
__device__ __forceinline__ unsigned smem_u32(const void* p) {
    unsigned a;
    asm("{ .reg .u64 t; cvta.to.shared.u64 t, %1; cvt.u32.u64 %0, t; }"
        : "=r"(a) : "l"(p));
    return a;
}
__device__ __forceinline__ unsigned fkey(float x) {
    int b = __float_as_int(x);
    return (unsigned)(b ^ ((b >> 31) | 0x80000000));
}
__device__ __forceinline__ float funkey(unsigned k) {
    int b = (k & 0x80000000u) ? (int)(k ^ 0x80000000u) : (int)(~k);
    return __int_as_float(b);
}
__device__ __forceinline__ unsigned redux_min_u32(unsigned x) {
    unsigned r;
    asm volatile("redux.sync.min.u32 %0, %1, 0xffffffff;" : "=r"(r) : "r"(x));
    return r;
}
__device__ __forceinline__ unsigned atom_acqrel_add_u32(unsigned* p, unsigned v) {
    unsigned old;
    asm volatile("atom.acq_rel.gpu.global.add.u32 %0, [%1], %2;"
                 : "=r"(old) : "l"(p), "r"(v) : "memory");
    return old;
}
__device__ __forceinline__ unsigned ld_acquire_u32(const unsigned* p) {
    unsigned v;
    asm volatile("ld.acquire.gpu.global.u32 %0, [%1];" : "=r"(v) : "l"(p)
                 : "memory");
    return v;
}
__device__ __forceinline__ void mbar_init(unsigned mbar, unsigned count) {
    asm volatile("mbarrier.init.shared.b64 [%0], %1;" :: "r"(mbar), "r"(count)
                 : "memory");
}
__device__ __forceinline__ void mbar_expect_tx(unsigned mbar, unsigned tx) {
    asm volatile("mbarrier.arrive.expect_tx.shared.b64 _, [%0], %1;"
                 :: "r"(mbar), "r"(tx) : "memory");
}
__device__ __forceinline__ void bulk_g2s(unsigned dst, const void* src,
                                         unsigned bytes, unsigned mbar) {
    asm volatile(
        "cp.async.bulk.shared::cluster.global.mbarrier::complete_tx::bytes "
        "[%0], [%1], %2, [%3];"
        :: "r"(dst), "l"(src), "r"(bytes), "r"(mbar) : "memory");
}
__device__ __forceinline__ void mbar_wait(unsigned mbar, unsigned parity) {
    unsigned done;
    asm volatile(
        "{\n\t.reg .pred p;\n\t"
        "mbarrier.try_wait.parity.acquire.cta.shared::cta.b64 p, [%1], %2;\n\t"
        "selp.b32 %0, 1, 0, p;\n\t}"
        : "=r"(done) : "r"(mbar), "r"(parity) : "memory");
    while (!done) {
        asm volatile(
            "{\n\t.reg .pred p;\n\t"
            "mbarrier.try_wait.parity.acquire.cta.shared::cta.b64 p, [%1], %2, 0x989680;\n\t"
            "selp.b32 %0, 1, 0, p;\n\t}"
            : "=r"(done) : "r"(mbar), "r"(parity) : "memory");
    }
}

// ---------------------------------------------------------------------------
// Fused cost+lsa, last-block-takes-over. Cost staging via cp.async.bulk
// (3 slots, depth-2) with EARLY refill: the k+2 copy is issued right after
// the iteration-k barrier (which already orders iter k-1's gathers of that
// slot). ONE __syncthreads/iteration. Arithmetic identical to R14 ->
// bit-identical cost output. Owning threads also write the example's
// 16-wide diagonal slice to g_diag for a dense lsa load.
// ---------------------------------------------------------------------------
__global__ __launch_bounds__(256)
void cost_lsa_kernel(const float* __restrict__ prel, const int* __restrict__ grel,
                     Ptrs ptrs, float* __restrict__ out) {
    __shared__ __align__(128) char smem_raw[3 * STAGE_BYTES + 32 + 256 + 64];
    // [0,24576) stages; [24576,24600) 3 mbars; [24608,24864) relp; [24864,...) red

    const int bex = (int)(blockIdx.x >> 6);          // example index

    // ========================= cost phase =========================
    {
        float (*stage)[SEQ] = (float (*)[SEQ])smem_raw;
        float (*relp)[32]   = (float (*)[32])(smem_raw + 3 * STAGE_BYTES + 32);
        float (*red)[8]     = (float (*)[8])(smem_raw + 3 * STAGE_BYTES + 32 + 256);

        const int row0 = blockIdx.x * 2;
        const int tid  = threadIdx.x;
        const int w    = tid >> 5;
        const int lane = tid & 31;

        const unsigned sbase = smem_u32(&stage[0][0]);
        const unsigned mbase = sbase + 3 * STAGE_BYTES;

        if (tid == 0) {
            mbar_init(mbase + 0, 1);
            mbar_init(mbase + 8, 1);
            mbar_init(mbase + 16, 1);
        }
        __syncthreads();            // mbar init visible to all waiters

        // prologue: iterations 0,1 in flight (depth-2), issued by tid 0
        if (tid == 0) {
            #pragma unroll
            for (int k = 0; k < 2; k++) {
                const float* src = ptrs.pos[k >> 1] + (size_t)(row0 + (k & 1)) * SEQ;
                mbar_expect_tx(mbase + 8u * k, STAGE_BYTES);
                bulk_g2s(sbase + (unsigned)k * STAGE_BYTES, src, STAGE_BYTES,
                         mbase + 8u * k);
            }
        }

        // rel-class softmax: warp 0 -> row0, warp 1 -> row0+1 (overlaps loads)
        if (tid < 64) {
            float e = (lane < NCLS) ? __expf(prel[(size_t)(row0 + w) * NCLS + lane]) : 0.f;
            float s = e;
            #pragma unroll
            for (int o = 16; o; o >>= 1) s += __shfl_xor_sync(0xffffffffu, s, o);
            if (lane < NCLS) relp[w][lane] = e / s;
        }
        __syncthreads();

        const int4 gr = ((const int4*)grel)[tid];
        float acc[2][4];
        #pragma unroll
        for (int r = 0; r < 2; r++) {
            acc[r][0] = relp[r][gr.x];
            acc[r][1] = relp[r][gr.y];
            acc[r][2] = relp[r][gr.z];
            acc[r][3] = relp[r][gr.w];
        }

        int4 gi;
        #pragma unroll
        for (int k = 0; k < NITER; k++) {
            const int d  = k >> 1;
            const int r  = k & 1;
            const int sb = k % 3;
            const int pb = k & 1;

            // wait for this iteration's bulk copy (phase flips per slot reuse)
            mbar_wait(mbase + 8u * sb, (unsigned)((k / 3) & 1));

            if (r == 0) gi = ((const int4*)ptrs.gidx[d])[tid];

            const float4* sp = (const float4*)&stage[sb][0];
            float4 x0 = sp[tid];
            float4 x1 = sp[tid + 256];
            float lsum = (__expf(x0.x) + __expf(x0.y)) + (__expf(x0.z) + __expf(x0.w))
                       + (__expf(x1.x) + __expf(x1.y)) + (__expf(x1.z) + __expf(x1.w));
            #pragma unroll
            for (int o = 16; o; o >>= 1) lsum += __shfl_xor_sync(0xffffffffu, lsum, o);
            if (lane == 0) red[pb][w] = lsum;
            __syncthreads();   // red visible; ALL threads past iter k-1's
                               // gathers of slot (k+2)%3 == (k-1)%3

            // EARLY refill: issue k+2 copy now (hazard cleared by the
            // barrier above), giving it an extra half-iteration of lead.
            if (k + 2 < NITER && tid == 0) {
                const int kn = k + 2;
                const float* src = ptrs.pos[kn >> 1] + (size_t)(row0 + (kn & 1)) * SEQ;
                const unsigned slot = (unsigned)(kn % 3);
                mbar_expect_tx(mbase + 8u * slot, STAGE_BYTES);
                bulk_g2s(sbase + slot * STAGE_BYTES, src, STAGE_BYTES,
                         mbase + 8u * slot);
            }

            float s = ((red[pb][0] + red[pb][1]) + (red[pb][2] + red[pb][3]))
                    + ((red[pb][4] + red[pb][5]) + (red[pb][6] + red[pb][7]));
            float inv = 1.0f / s;

            acc[r][0] += __expf(stage[sb][gi.x]) * inv;
            acc[r][1] += __expf(stage[sb][gi.y]) * inv;
            acc[r][2] += __expf(stage[sb][gi.z]) * inv;
            acc[r][3] += __expf(stage[sb][gi.w]) * inv;
        }

        #pragma unroll
        for (int r = 0; r < 2; r++) {
            float4 res = make_float4(-acc[r][0], -acc[r][1], -acc[r][2], -acc[r][3]);
            ((float4*)(out + (size_t)(row0 + r) * TGOLD))[tid] = res;
            // diagonal slice: thread 4*bex+q owns gold cols 16*bex+4q..+3
            if ((tid >> 2) == bex) {
                float4* dd = (float4*)&g_diag[bex][(row0 & 127) + r][(tid & 3) * 4];
                *dd = res;
            }
        }
    }

    // ================= completion + last-block takeover =================
    __syncthreads();                                  // all STGs hb-before tid0
    int last = 0;
    if (threadIdx.x == 0)
        last = ((atom_acqrel_add_u32(&g_cnt[bex], 1u) & 63u) == 63u);
    if (threadIdx.x >= 32) return;                    // warps 1-7 done

    const int lane = threadIdx.x;
    last = __shfl_sync(0xffffffffu, last, 0);
    if (!last) return;

    (void)ld_acquire_u32(&g_cnt[bex]);                // per-lane acquire
    const int b = bex;

    // ========================= lsa phase (warp 0) =========================
    float* Cf = (float*)smem_raw;                 // 8 KB (reuse)
    int*   x  = (int*)(smem_raw + 8192);          // 64 B (row -> col)

    // dense 8 KB load from the compact diagonal buffer
    for (int j = lane; j < NGEN; j += 32) {
        const float4* src = (const float4*)&g_diag[b][j][0];
        #pragma unroll
        for (int q = 0; q < 4; q++) {
            float4 f = src[q];
            Cf[(q * 4 + 0) * NGEN + j] = f.x;
            Cf[(q * 4 + 1) * NGEN + j] = f.y;
            Cf[(q * 4 + 2) * NGEN + j] = f.z;
            Cf[(q * 4 + 3) * NGEN + j] = f.w;
        }
    }
    __syncwarp();

    float vreg[4];                 // v[j], j = lane + 32*t (ZERO init:
    int   yreg[4];                 //   rectangular dual feasibility)
    #pragma unroll
    for (int t = 0; t < 4; t++) { vreg[t] = 0.f; yreg[t] = -1; }

    for (int f = 0; f < G; f++) {
        float dreg[4];
        int   pr[4];
        #pragma unroll
        for (int t = 0; t < 4; t++) {
            dreg[t] = Cf[f * NGEN + lane + 32 * t] - vreg[t];
            pr[t] = f;
        }
        unsigned scan = 0;
        int jmin;
        float mu;

        while (true) {
            unsigned bestk = 0xFFFFFFFFu;
            unsigned bestj = 0xFFFFFFFFu;
            #pragma unroll
            for (int t = 0; t < 4; t++) {
                if (!((scan >> t) & 1u)) {
                    unsigned k = fkey(dreg[t]);
                    if (k < bestk) { bestk = k; bestj = (unsigned)(lane + 32 * t); }
                }
            }
            unsigned kmin = redux_min_u32(bestk);
            unsigned j1   = redux_min_u32((bestk == kmin) ? bestj : 0xFFFFFFFFu);
            mu   = funkey(kmin);
            jmin = (int)j1;

            const int tt = jmin >> 5, sl = jmin & 31;
            if (sl == lane) scan |= 1u << tt;

            int   ysel = (tt == 0) ? yreg[0] : (tt == 1) ? yreg[1]
                       : (tt == 2) ? yreg[2] : yreg[3];
            float vsel = (tt == 0) ? vreg[0] : (tt == 1) ? vreg[1]
                       : (tt == 2) ? vreg[2] : vreg[3];
            int   i1 = __shfl_sync(0xffffffffu, ysel, sl);
            float vj = __shfl_sync(0xffffffffu, vsel, sl);
            if (i1 < 0) break;

            float ui = Cf[i1 * NGEN + jmin] - vj;

            #pragma unroll
            for (int t = 0; t < 4; t++) {
                if (!((scan >> t) & 1u)) {
                    int j = lane + 32 * t;
                    float nd = mu + (Cf[i1 * NGEN + j] - vreg[t]) - ui;
                    if (nd < dreg[t]) { dreg[t] = nd; pr[t] = i1; }
                }
            }
        }

        // deferred potential update over scanned columns
        #pragma unroll
        for (int t = 0; t < 4; t++)
            if ((scan >> t) & 1u) vreg[t] += dreg[t] - mu;

        // augment along pred chain
        int j = jmin;
        while (true) {
            const int tt = j >> 5, sl = j & 31;
            int psel = (tt == 0) ? pr[0] : (tt == 1) ? pr[1]
                     : (tt == 2) ? pr[2] : pr[3];
            int i = __shfl_sync(0xffffffffu, psel, sl);
            if ((j & 31) == lane) yreg[j >> 5] = i;   // y[j] = i
            int jn = 0;
            if (lane == 0) {
                jn = (i == f) ? -1 : x[i];
                x[i] = j;
            }
            jn = __shfl_sync(0xffffffffu, jn, 0);
            if (i == f) break;
            j = jn;
        }
        __syncwarp();
    }

    // transposed return: col[i] = x[i]; order = argsort(col)
    if (lane < G) {
        float* rows_out = (float*)(out + COST_ELEMS);
        float* cols_out = rows_out + (size_t)BSZ * G;
        int c = x[lane];
        int rank = 0;
        #pragma unroll
        for (int r2 = 0; r2 < G; r2++) rank += (x[r2] < c) ? 1 : 0;
        rows_out[b * G + rank] = (float)c;
        cols_out[b * G + rank] = (float)lane;
    }
}

// ---------------------------------------------------------------------------
// Launch — single kernel, no init (modulo counters)
// ---------------------------------------------------------------------------
extern "C" void kernel_launch(void* const* d_in, const int* in_sizes, int n_in,
                              void* d_out, int out_size) {
    const float* prel = (const float*)d_in[0];
    Ptrs ptrs;
    for (int d = 0; d < 8; d++) ptrs.pos[d]  = (const float*)d_in[1 + d];
    const int* grel = (const int*)d_in[9];
    for (int d = 0; d < 8; d++) ptrs.gidx[d] = (const int*)d_in[10 + d];

    float* out = (float*)d_out;

    cost_lsa_kernel<<<(BSZ * NGEN) / 2, 256>>>(prel, grel, ptrs, out);
}